// round 10
// baseline (speedup 1.0000x reference)
#include <cuda_runtime.h>
#include <cuda_bf16.h>
#include <cstdint>

#define H 64
#define TS 24
#define NSTORE 20000
#define NREG 2000
#define E_SS 640000
#define E_RS 160000
#define ALPHA 0.5f

// ---------------- device scratch ----------------
__device__ float g_hs[NSTORE * H];
__device__ float g_hr[NREG * H];
__device__ float g_afwd[NSTORE * H];
__device__ float g_arev[NSTORE * H];
__device__ float g_ars[NSTORE * H];
__device__ int g_cnt[3 * NSTORE];
__device__ int g_off[3 * (NSTORE + 1)];
__device__ int g_cur[3 * NSTORE];
__device__ int g_csr_fwd[E_SS];
__device__ int g_csr_rev[E_SS];
__device__ int g_csr_rs[E_RS];

// ---------------- helpers ----------------
__device__ __forceinline__ float rcpf(float x) {
    float y; asm("rcp.approx.f32 %0, %1;" : "=f"(y) : "f"(x)); return y;
}

// bf16 mma (base PTX, sm_80+; HMMA pipe)
#define MMA_BF16(d, a, b) \
    asm volatile("mma.sync.aligned.m16n8k16.row.col.f32.bf16.bf16.f32 " \
        "{%0,%1,%2,%3}, {%4,%5,%6,%7}, {%8,%9}, {%0,%1,%2,%3};" \
        : "+f"((d)[0]), "+f"((d)[1]), "+f"((d)[2]), "+f"((d)[3]) \
        : "r"((a)[0]), "r"((a)[1]), "r"((a)[2]), "r"((a)[3]), \
          "r"((b)[0]), "r"((b)[1]))

__device__ __forceinline__ void ldsm_x4(uint32_t* r, uint32_t addr) {
    asm volatile("ldmatrix.sync.aligned.m8n8.x4.shared.b16 {%0,%1,%2,%3}, [%4];"
        : "=r"(r[0]), "=r"(r[1]), "=r"(r[2]), "=r"(r[3]) : "r"(addr));
}

// ---------------- CSR build ----------------
__global__ void zero_cnt_kernel() {
    int i = blockIdx.x * blockDim.x + threadIdx.x;
    if (i < 3 * NSTORE) g_cnt[i] = 0;
}

__global__ void count_kernel(const int* __restrict__ src, const int* __restrict__ dst,
                             const int* __restrict__ rs_dst) {
    int e = blockIdx.x * blockDim.x + threadIdx.x;
    if (e < E_SS) {
        atomicAdd(&g_cnt[dst[e]], 1);
        atomicAdd(&g_cnt[NSTORE + src[e]], 1);
    }
    if (e < E_RS) atomicAdd(&g_cnt[2 * NSTORE + rs_dst[e]], 1);
}

// One-pass scan: 1024 threads x 20 items/thread (20480 >= 20000).
__global__ void scan_kernel() {
    __shared__ int ssum[1024];
    const int seg = blockIdx.x;
    const int base = seg * NSTORE;
    const int tid = threadIdx.x;
    const int start = tid * 20;
    int local[20];
    int sum = 0;
#pragma unroll
    for (int j = 0; j < 20; j++) {
        int i = start + j;
        int v = (i < NSTORE) ? g_cnt[base + i] : 0;
        local[j] = sum;
        sum += v;
    }
    ssum[tid] = sum;
    __syncthreads();
    for (int ofs = 1; ofs < 1024; ofs <<= 1) {
        int y = (tid >= ofs) ? ssum[tid - ofs] : 0;
        __syncthreads();
        ssum[tid] += y;
        __syncthreads();
    }
    int excl = (tid > 0) ? ssum[tid - 1] : 0;
#pragma unroll
    for (int j = 0; j < 20; j++) {
        int i = start + j;
        if (i < NSTORE) {
            int e = excl + local[j];
            g_off[seg * (NSTORE + 1) + i] = e;
            g_cur[base + i] = e;
        }
    }
    if (tid == 1023) g_off[seg * (NSTORE + 1) + NSTORE] = ssum[1023];
}

__global__ void scatter_kernel(const int* __restrict__ src, const int* __restrict__ dst,
                               const int* __restrict__ rs_src, const int* __restrict__ rs_dst) {
    int e = blockIdx.x * blockDim.x + threadIdx.x;
    if (e < E_SS) {
        int s = src[e], d = dst[e];
        g_csr_fwd[atomicAdd(&g_cur[d], 1)] = s;
        g_csr_rev[atomicAdd(&g_cur[NSTORE + s], 1)] = d;
    }
    if (e < E_RS) {
        g_csr_rs[atomicAdd(&g_cur[2 * NSTORE + rs_dst[e]], 1)] = rs_src[e];
    }
}

// ---------------- gather (mean), 4-edge unrolled ----------------
#define GATHER_WARPS 8
__global__ __launch_bounds__(256)
void gather_kernel() {
    int gw = blockIdx.x * GATHER_WARPS + (threadIdx.x >> 5);
    int lane = threadIdx.x & 31;
    int seg, node;
    if (gw < NSTORE)          { seg = 0; node = gw; }
    else if (gw < 2 * NSTORE) { seg = 1; node = gw - NSTORE; }
    else if (gw < 3 * NSTORE) { seg = 2; node = gw - 2 * NSTORE; }
    else return;

    const int* off = &g_off[seg * (NSTORE + 1)];
    int start = off[node], end = off[node + 1];
    const int* lst = (seg == 0) ? g_csr_fwd : (seg == 1) ? g_csr_rev : g_csr_rs;
    const float* feat = (seg == 2) ? g_hr : g_hs;

    float ax = 0.f, ay = 0.f, bx = 0.f, by = 0.f;
    float cx = 0.f, cy = 0.f, dx = 0.f, dy = 0.f;
    int e = start;
    for (; e + 3 < end; e += 4) {
        int n0 = __ldg(&lst[e]);
        int n1 = __ldg(&lst[e + 1]);
        int n2 = __ldg(&lst[e + 2]);
        int n3 = __ldg(&lst[e + 3]);
        float2 v0 = *(const float2*)&feat[n0 * H + lane * 2];
        float2 v1 = *(const float2*)&feat[n1 * H + lane * 2];
        float2 v2 = *(const float2*)&feat[n2 * H + lane * 2];
        float2 v3 = *(const float2*)&feat[n3 * H + lane * 2];
        ax += v0.x; ay += v0.y;
        bx += v1.x; by += v1.y;
        cx += v2.x; cy += v2.y;
        dx += v3.x; dy += v3.y;
    }
    for (; e < end; e++) {
        int n0 = __ldg(&lst[e]);
        float2 v0 = *(const float2*)&feat[n0 * H + lane * 2];
        ax += v0.x; ay += v0.y;
    }
    ax += bx + cx + dx;
    ay += by + cy + dy;
    float inv = (end > start) ? __fdividef(1.f, (float)(end - start)) : 0.f;
    float* out = (seg == 0) ? g_afwd : (seg == 1) ? g_arev : g_ars;
    *(float2*)&out[node * H + lane * 2] = make_float2(ax * inv, ay * inv);
}

// ---------------- mma.sync LSTM (ldmatrix + shared-rcp epilogue) ----------------
#define LS_M 80
#define LS_THREADS 256
#define LS_BLOCKS_S (NSTORE / LS_M)   // 250
#define LS_BLOCKS_R (NREG / LS_M)     // 25

#define OFF_WFRAG 0                   // 16384 u32 = 64 KB
#define OFF_HHI   65536               // 80 x 72 bf16 = 11520 B
#define OFF_HLO   (OFF_HHI + 11520)
#define OFF_XT    (OFF_HLO + 11520)   // 24 x 80 f32
#define OFF_WIN   (OFF_XT + 7680)
#define OFF_BG    (OFF_WIN + 1024)
#define LS_SMEM   (OFF_BG + 1024)     // 98304 B

__global__ __launch_bounds__(LS_THREADS, 2)
void lstm_mma_kernel(const float* __restrict__ x_s, const float* __restrict__ x_r,
                     const float* __restrict__ Wih_s, const float* __restrict__ Whh_s,
                     const float* __restrict__ bih_s, const float* __restrict__ bhh_s,
                     const float* __restrict__ Wih_r, const float* __restrict__ Whh_r,
                     const float* __restrict__ bih_r, const float* __restrict__ bhh_r)
{
    extern __shared__ char smem[];
    uint32_t* Wfrag = (uint32_t*)(smem + OFF_WFRAG);
    __nv_bfloat16* hHi = (__nv_bfloat16*)(smem + OFF_HHI);
    __nv_bfloat16* hLo = (__nv_bfloat16*)(smem + OFF_HLO);
    float* xT   = (float*)(smem + OFF_XT);
    float* winG = (float*)(smem + OFF_WIN);
    float* bG   = (float*)(smem + OFF_BG);

    const int tid = threadIdx.x;
    const bool is_store = (blockIdx.x < LS_BLOCKS_S);
    const int lb = is_store ? blockIdx.x : (blockIdx.x - LS_BLOCKS_S);
    const float* x   = is_store ? x_s   : x_r;
    const float* Wih = is_store ? Wih_s : Wih_r;
    const float* Whh = is_store ? Whh_s : Whh_r;
    const float* bih = is_store ? bih_s : bih_r;
    const float* bhh = is_store ? bhh_s : bhh_r;
    float* hout = is_store ? g_hs : g_hr;
    const int s0 = lb * LS_M;

    // ---- build W fragments (b-frag order) ----
    for (int idx = tid; idx < 16384; idx += LS_THREADS) {
        int ln   = idx & 31;
        int reg  = (idx >> 5) & 1;
        int nt   = (idx >> 6) & 15;
        int ks   = (idx >> 10) & 3;
        int hl   = (idx >> 12) & 1;
        int half = (idx >> 13) & 1;
        int tgi = ln & 3, gidi = ln >> 2;
        int gate = (nt & 1) * 2 + (gidi & 1);
        int unit = half * 32 + (nt >> 1) * 4 + (gidi >> 1);
        int row = gate * 64 + unit;
        int k = ks * 16 + tgi * 2 + reg * 8;
        float w0 = Whh[row * 64 + k];
        float w1 = Whh[row * 64 + k + 1];
        __nv_bfloat16 h0 = __float2bfloat16(w0);
        __nv_bfloat16 h1 = __float2bfloat16(w1);
        uint32_t val;
        if (hl == 0) {
            val = (uint32_t)__bfloat16_as_ushort(h0)
                | ((uint32_t)__bfloat16_as_ushort(h1) << 16);
        } else {
            __nv_bfloat16 l0 = __float2bfloat16(w0 - __bfloat162float(h0));
            __nv_bfloat16 l1 = __float2bfloat16(w1 - __bfloat162float(h1));
            val = (uint32_t)__bfloat16_as_ushort(l0)
                | ((uint32_t)__bfloat16_as_ushort(l1) << 16);
        }
        Wfrag[idx] = val;
    }
    if (tid < 256) {
        int half = tid >> 7, rr = tid & 127;
        int nt = (rr >> 3) & 15, g8 = rr & 7;
        int gate = (nt & 1) * 2 + (g8 & 1);
        int unit = half * 32 + (nt >> 1) * 4 + (g8 >> 1);
        winG[tid] = Wih[gate * 64 + unit];
        bG[tid]   = bih[gate * 64 + unit] + bhh[gate * 64 + unit];
    }
    for (int i = tid; i < 23040 / 4; i += LS_THREADS)
        ((uint32_t*)(smem + OFF_HHI))[i] = 0;
    for (int i = tid; i < LS_M * TS; i += LS_THREADS) {
        int s = i / TS, t = i % TS;
        xT[t * LS_M + s] = x[(s0 + s) * TS + t];
    }
    __syncthreads();

    const int warp = tid >> 5, lane = tid & 31;
    const int tg = lane & 3, gid = lane >> 2;

    // ldmatrix per-lane address offset (mat = lane>>3, r8 = lane&7)
    const int mat = lane >> 3, r8 = lane & 7;
    const uint32_t sbase32 = (uint32_t)__cvta_generic_to_shared(smem);
    const uint32_t aoff = (uint32_t)(((mat & 1) * 8 + r8) * 144 + (mat >> 1) * 16);
    const uint32_t aHiB = sbase32 + OFF_HHI + aoff;
    const uint32_t aLoB = sbase32 + OFF_HLO + aoff;

    float cst[2][10];
#pragma unroll
    for (int i = 0; i < 10; i++) { cst[0][i] = 0.f; cst[1][i] = 0.f; }

    for (int t = 0; t < TS; t++) {
        float hn[2][10];
        float xa[5], xb[5];
#pragma unroll
        for (int mt = 0; mt < 5; mt++) {
            xa[mt] = xT[t * LS_M + mt * 16 + gid];
            xb[mt] = xT[t * LS_M + mt * 16 + gid + 8];
        }
#pragma unroll
        for (int half = 0; half < 2; half++) {
            float acc[5][2][4];
#pragma unroll
            for (int t01 = 0; t01 < 2; t01++) {
                int r0 = half * 128 + (2 * warp + t01) * 8 + 2 * tg;
                float w0 = winG[r0], w1 = winG[r0 + 1];
                float bb0 = bG[r0], bb1 = bG[r0 + 1];
#pragma unroll
                for (int mt = 0; mt < 5; mt++) {
                    acc[mt][t01][0] = fmaf(xa[mt], w0, bb0);
                    acc[mt][t01][1] = fmaf(xa[mt], w1, bb1);
                    acc[mt][t01][2] = fmaf(xb[mt], w0, bb0);
                    acc[mt][t01][3] = fmaf(xb[mt], w1, bb1);
                }
            }
#pragma unroll
            for (int ks = 0; ks < 4; ks++) {
                uint32_t a[5][4];
#pragma unroll
                for (int mt = 0; mt < 5; mt++)
                    ldsm_x4(a[mt], aHiB + mt * 2304 + ks * 32);
                uint32_t bhi[2][2], blo[2][2];
#pragma unroll
                for (int t01 = 0; t01 < 2; t01++) {
                    int nt = 2 * warp + t01;
                    int ih = ((((half * 2 + 0) * 4 + ks) * 16 + nt) * 2) * 32 + lane;
                    int il = ((((half * 2 + 1) * 4 + ks) * 16 + nt) * 2) * 32 + lane;
                    bhi[t01][0] = Wfrag[ih];
                    bhi[t01][1] = Wfrag[ih + 32];
                    blo[t01][0] = Wfrag[il];
                    blo[t01][1] = Wfrag[il + 32];
                }
#pragma unroll
                for (int mt = 0; mt < 5; mt++) {
                    MMA_BF16(acc[mt][0], a[mt], bhi[0]);
                    MMA_BF16(acc[mt][1], a[mt], bhi[1]);
                    MMA_BF16(acc[mt][0], a[mt], blo[0]);
                    MMA_BF16(acc[mt][1], a[mt], blo[1]);
                }
#pragma unroll
                for (int mt = 0; mt < 5; mt++)
                    ldsm_x4(a[mt], aLoB + mt * 2304 + ks * 32);
#pragma unroll
                for (int mt = 0; mt < 5; mt++) {
                    MMA_BF16(acc[mt][0], a[mt], bhi[0]);
                    MMA_BF16(acc[mt][1], a[mt], bhi[1]);
                }
            }
            // epilogue: cell pair with shared reciprocals (exact algebra)
#pragma unroll
            for (int mt = 0; mt < 5; mt++) {
                float gi0 = acc[mt][0][0], gf0 = acc[mt][0][1];
                float gg0 = acc[mt][1][0], go0 = acc[mt][1][1];
                float gi1 = acc[mt][0][2], gf1 = acc[mt][0][3];
                float gg1 = acc[mt][1][2], go1 = acc[mt][1][3];

                float e0 = __expf(-gi0), e1 = __expf(-gf0);
                float e2 = __expf(-go0), e3 = __expf(-2.f * gg0);
                float e4 = __expf(-gi1), e5 = __expf(-gf1);
                float e6 = __expf(-go1), e7 = __expf(-2.f * gg1);
                float d0 = 1.f + e0, d1 = 1.f + e1, d2 = 1.f + e2, d3 = 1.f + e3;
                float d4 = 1.f + e4, d5 = 1.f + e5, d6 = 1.f + e6, d7 = 1.f + e7;
                float p01 = d0 * d1, p23 = d2 * d3, p45 = d4 * d5, p67 = d6 * d7;
                float p0123 = p01 * p23, p4567 = p45 * p67;
                float r = rcpf(p0123 * p4567);
                float r0123 = r * p4567, r4567 = r * p0123;
                float i01 = r0123 * p23, i23 = r0123 * p01;
                float i45 = r4567 * p67, i67 = r4567 * p45;
                float si0 = i01 * d1, sf0 = i01 * d0, so0 = i23 * d3;
                float tg0 = (1.f - e3) * (i23 * d2);
                float si1 = i45 * d5, sf1 = i45 * d4, so1 = i67 * d7;
                float tg1 = (1.f - e7) * (i67 * d6);

                float cc0 = fmaf(sf0, cst[half][mt * 2 + 0], si0 * tg0);
                float cc1 = fmaf(sf1, cst[half][mt * 2 + 1], si1 * tg1);
                cst[half][mt * 2 + 0] = cc0;
                cst[half][mt * 2 + 1] = cc1;
                float ea = __expf(-2.f * cc0), eb = __expf(-2.f * cc1);
                float da = 1.f + ea, db = 1.f + eb;
                float r2 = rcpf(da * db);
                hn[half][mt * 2 + 0] = so0 * ((1.f - ea) * (r2 * db));
                hn[half][mt * 2 + 1] = so1 * ((1.f - eb) * (r2 * da));
            }
        }
        __syncthreads();
#pragma unroll
        for (int half = 0; half < 2; half++) {
            int u = half * 32 + warp * 4 + tg;
#pragma unroll
            for (int mt = 0; mt < 5; mt++) {
#pragma unroll
                for (int sb = 0; sb < 2; sb++) {
                    int s = mt * 16 + gid + sb * 8;
                    float h = hn[half][mt * 2 + sb];
                    __nv_bfloat16 hh = __float2bfloat16(h);
                    __nv_bfloat16 hl = __float2bfloat16(h - __bfloat162float(hh));
                    hHi[s * 72 + u] = hh;
                    hLo[s * 72 + u] = hl;
                }
            }
        }
        __syncthreads();
    }

    // final h write (h = hi + lo; err ~2^-17, coalesced)
    for (int i = tid; i < LS_M * H; i += LS_THREADS) {
        int s = i >> 6, u = i & 63;
        float h = __bfloat162float(hHi[s * 72 + u]) + __bfloat162float(hLo[s * 72 + u]);
        hout[(s0 + s) * H + u] = h;
    }
}

// ---------------- fused finalize (64 nodes/block) ----------------
#define FIN_NODES 64
#define FIN_THREADS 1024
#define FIN_WS 65
#define FIN_SMEM_FLOATS (5 * H * FIN_WS + FIN_NODES * 4 * H + FIN_NODES * H + 2 * H)

__global__ __launch_bounds__(FIN_THREADS, 1)
void finalize_kernel(const float* __restrict__ W_s2d, const float* __restrict__ b_s2d,
                     const float* __restrict__ W_d2s, const float* __restrict__ b_d2s,
                     const float* __restrict__ W_self, const float* __restrict__ b_self,
                     const float* __restrict__ Wl_rs, const float* __restrict__ bl_rs,
                     const float* __restrict__ Wr_rs,
                     const float* __restrict__ Wf, const float* __restrict__ bf,
                     float* __restrict__ out)
{
    extern __shared__ float smemf[];
    float* Wsum = smemf;
    float* Wa   = Wsum + H * FIN_WS;
    float* Wb   = Wa + H * FIN_WS;
    float* Wc   = Wb + H * FIN_WS;
    float* Wfo  = Wc + H * FIN_WS;
    float* vec  = Wfo + H * FIN_WS;
    float* shm  = vec + FIN_NODES * 4 * H;
    float* btot = shm + FIN_NODES * H;
    float* bfv  = btot + H;

    const int tid = threadIdx.x;
    const int n0 = blockIdx.x * FIN_NODES;

    for (int i = tid; i < H * H; i += FIN_THREADS) {
        int r = i >> 6, cix = i & 63;
        Wsum[r * FIN_WS + cix] = W_self[i] + Wr_rs[i];
        Wa[r * FIN_WS + cix]   = W_s2d[i];
        Wb[r * FIN_WS + cix]   = W_d2s[i];
        Wc[r * FIN_WS + cix]   = Wl_rs[i];
        Wfo[r * FIN_WS + cix]  = Wf[i];
    }
    if (tid < H) {
        btot[tid] = b_self[tid] + bl_rs[tid]
                  + (1.f - ALPHA) * b_s2d[tid] + ALPHA * b_d2s[tid];
        bfv[tid] = bf[tid];
    }
    for (int i = tid; i < FIN_NODES * 4 * H; i += FIN_THREADS) {
        int n = i >> 8, v = (i >> 6) & 3, k = i & 63;
        int node = n0 + n;
        float val = 0.f;
        if (node < NSTORE) {
            if (v == 0)      val = g_hs[node * H + k];
            else if (v == 1) val = (1.f - ALPHA) * g_afwd[node * H + k];
            else if (v == 2) val = ALPHA * g_arev[node * H + k];
            else             val = g_ars[node * H + k];
        }
        vec[i] = val;
    }
    __syncthreads();

    const int nq = tid >> 6, u = tid & 63;
#pragma unroll
    for (int g = 0; g < 4; g++) {
        int n = nq + 16 * g;
        const float* v0 = &vec[(n * 4 + 0) * H];
        const float* v1 = &vec[(n * 4 + 1) * H];
        const float* v2 = &vec[(n * 4 + 2) * H];
        const float* v3 = &vec[(n * 4 + 3) * H];
        float acc = btot[u];
#pragma unroll 8
        for (int k = 0; k < H; k++) {
            acc = fmaf(v0[k], Wsum[u * FIN_WS + k], acc);
            acc = fmaf(v1[k], Wa[u * FIN_WS + k], acc);
            acc = fmaf(v2[k], Wb[u * FIN_WS + k], acc);
            acc = fmaf(v3[k], Wc[u * FIN_WS + k], acc);
        }
        shm[n * H + u] = fmaxf(0.f, v0[u] + 0.5f * acc);
    }
    __syncthreads();

#pragma unroll
    for (int g = 0; g < 4; g++) {
        int n = nq + 16 * g;
        float acc2 = bfv[u];
#pragma unroll 8
        for (int k = 0; k < H; k++)
            acc2 = fmaf(Wfo[u * FIN_WS + k], shm[n * H + k], acc2);
        int node = n0 + n;
        if (node < NSTORE) out[node * H + u] = acc2;
    }
}

// ---------------- launch ----------------
extern "C" void kernel_launch(void* const* d_in, const int* in_sizes, int n_in,
                              void* d_out, int out_size)
{
    const float* x_store  = (const float*)d_in[0];
    const float* x_region = (const float*)d_in[1];
    const int* ess    = (const int*)d_in[2];
    const int* rs_src = (const int*)d_in[3];
    const int* rs_dst = (const int*)d_in[4];
    const float* Wih_s = (const float*)d_in[7];
    const float* Whh_s = (const float*)d_in[8];
    const float* bih_s = (const float*)d_in[9];
    const float* bhh_s = (const float*)d_in[10];
    const float* Wih_r = (const float*)d_in[11];
    const float* Whh_r = (const float*)d_in[12];
    const float* bih_r = (const float*)d_in[13];
    const float* bhh_r = (const float*)d_in[14];
    const float* W_s2d = (const float*)d_in[15];
    const float* b_s2d = (const float*)d_in[16];
    const float* W_d2s = (const float*)d_in[17];
    const float* b_d2s = (const float*)d_in[18];
    const float* W_self = (const float*)d_in[19];
    const float* b_self = (const float*)d_in[20];
    const float* Wl_rs = (const float*)d_in[21];
    const float* bl_rs = (const float*)d_in[22];
    const float* Wr_rs = (const float*)d_in[23];
    const float* Wf = (const float*)d_in[27];
    const float* bf = (const float*)d_in[28];

    static cudaStream_t s_side = nullptr;
    static cudaEvent_t ev_fork = nullptr, ev_join = nullptr;
    if (!s_side) {
        cudaStreamCreateWithFlags(&s_side, cudaStreamNonBlocking);
        cudaEventCreateWithFlags(&ev_fork, cudaEventDisableTiming);
        cudaEventCreateWithFlags(&ev_join, cudaEventDisableTiming);
    }

    const size_t fin_smem = FIN_SMEM_FLOATS * sizeof(float);
    cudaFuncSetAttribute(lstm_mma_kernel, cudaFuncAttributeMaxDynamicSharedMemorySize, LS_SMEM);
    cudaFuncSetAttribute(finalize_kernel, cudaFuncAttributeMaxDynamicSharedMemorySize, (int)fin_smem);

    // Fork: CSR build on side stream, LSTM on main stream.
    cudaEventRecord(ev_fork, 0);
    cudaStreamWaitEvent(s_side, ev_fork, 0);

    zero_cnt_kernel<<<(3 * NSTORE + 255) / 256, 256, 0, s_side>>>();
    count_kernel<<<(E_SS + 255) / 256, 256, 0, s_side>>>(ess, ess + E_SS, rs_dst);
    scan_kernel<<<3, 1024, 0, s_side>>>();

    lstm_mma_kernel<<<LS_BLOCKS_S + LS_BLOCKS_R, LS_THREADS, LS_SMEM>>>(
        x_store, x_region,
        Wih_s, Whh_s, bih_s, bhh_s,
        Wih_r, Whh_r, bih_r, bhh_r);

    scatter_kernel<<<(E_SS + 255) / 256, 256, 0, s_side>>>(ess, ess + E_SS, rs_src, rs_dst);

    cudaEventRecord(ev_join, s_side);
    cudaStreamWaitEvent(0, ev_join, 0);

    gather_kernel<<<(3 * NSTORE + GATHER_WARPS - 1) / GATHER_WARPS, 256>>>();

    finalize_kernel<<<(NSTORE + FIN_NODES - 1) / FIN_NODES, FIN_THREADS, fin_smem>>>(
        W_s2d, b_s2d, W_d2s, b_d2s, W_self, b_self,
        Wl_rs, bl_rs, Wr_rs, Wf, bf, (float*)d_out);
}

// round 11
// speedup vs baseline: 1.2838x; 1.2838x over previous
#include <cuda_runtime.h>
#include <cuda_bf16.h>
#include <cstdint>

#define H 64
#define TS 24
#define NSTORE 20000
#define NREG 2000
#define E_SS 640000
#define E_RS 160000
#define ALPHA 0.5f

// ---------------- device scratch ----------------
__device__ float g_hs[NSTORE * H];
__device__ float g_hr[NREG * H];
__device__ float g_afwd[NSTORE * H];
__device__ float g_arev[NSTORE * H];
__device__ float g_ars[NSTORE * H];
__device__ int g_cnt[3 * NSTORE];
__device__ int g_off[3 * (NSTORE + 1)];
__device__ int g_cur[3 * NSTORE];
__device__ int g_csr_fwd[E_SS];
__device__ int g_csr_rev[E_SS];
__device__ int g_csr_rs[E_RS];

// ---------------- helpers ----------------
__device__ __forceinline__ float rcpf(float x) {
    float y; asm("rcp.approx.f32 %0, %1;" : "=f"(y) : "f"(x)); return y;
}

// bf16 mma (base PTX, sm_80+; HMMA pipe)
#define MMA_BF16(d, a, b) \
    asm volatile("mma.sync.aligned.m16n8k16.row.col.f32.bf16.bf16.f32 " \
        "{%0,%1,%2,%3}, {%4,%5,%6,%7}, {%8,%9}, {%0,%1,%2,%3};" \
        : "+f"((d)[0]), "+f"((d)[1]), "+f"((d)[2]), "+f"((d)[3]) \
        : "r"((a)[0]), "r"((a)[1]), "r"((a)[2]), "r"((a)[3]), \
          "r"((b)[0]), "r"((b)[1]))

// ---------------- CSR build ----------------
__global__ void zero_cnt_kernel() {
    int i = blockIdx.x * blockDim.x + threadIdx.x;
    if (i < 3 * NSTORE) g_cnt[i] = 0;
}

__global__ void count_kernel(const int* __restrict__ src, const int* __restrict__ dst,
                             const int* __restrict__ rs_dst) {
    int e = blockIdx.x * blockDim.x + threadIdx.x;
    if (e < E_SS) {
        atomicAdd(&g_cnt[dst[e]], 1);
        atomicAdd(&g_cnt[NSTORE + src[e]], 1);
    }
    if (e < E_RS) atomicAdd(&g_cnt[2 * NSTORE + rs_dst[e]], 1);
}

// One-pass scan: 1024 threads x 20 items/thread (20480 >= 20000).
__global__ void scan_kernel() {
    __shared__ int ssum[1024];
    const int seg = blockIdx.x;
    const int base = seg * NSTORE;
    const int tid = threadIdx.x;
    const int start = tid * 20;
    int local[20];
    int sum = 0;
#pragma unroll
    for (int j = 0; j < 20; j++) {
        int i = start + j;
        int v = (i < NSTORE) ? g_cnt[base + i] : 0;
        local[j] = sum;
        sum += v;
    }
    ssum[tid] = sum;
    __syncthreads();
    for (int ofs = 1; ofs < 1024; ofs <<= 1) {
        int y = (tid >= ofs) ? ssum[tid - ofs] : 0;
        __syncthreads();
        ssum[tid] += y;
        __syncthreads();
    }
    int excl = (tid > 0) ? ssum[tid - 1] : 0;
#pragma unroll
    for (int j = 0; j < 20; j++) {
        int i = start + j;
        if (i < NSTORE) {
            int e = excl + local[j];
            g_off[seg * (NSTORE + 1) + i] = e;
            g_cur[base + i] = e;
        }
    }
    if (tid == 1023) g_off[seg * (NSTORE + 1) + NSTORE] = ssum[1023];
}

__global__ void scatter_kernel(const int* __restrict__ src, const int* __restrict__ dst,
                               const int* __restrict__ rs_src, const int* __restrict__ rs_dst) {
    int e = blockIdx.x * blockDim.x + threadIdx.x;
    if (e < E_SS) {
        int s = src[e], d = dst[e];
        g_csr_fwd[atomicAdd(&g_cur[d], 1)] = s;
        g_csr_rev[atomicAdd(&g_cur[NSTORE + s], 1)] = d;
    }
    if (e < E_RS) {
        g_csr_rs[atomicAdd(&g_cur[2 * NSTORE + rs_dst[e]], 1)] = rs_src[e];
    }
}

// ---------------- gather (mean), 2-edge unrolled ----------------
#define GATHER_WARPS 8
__global__ __launch_bounds__(256)
void gather_kernel() {
    int gw = blockIdx.x * GATHER_WARPS + (threadIdx.x >> 5);
    int lane = threadIdx.x & 31;
    int seg, node;
    if (gw < NSTORE)          { seg = 0; node = gw; }
    else if (gw < 2 * NSTORE) { seg = 1; node = gw - NSTORE; }
    else if (gw < 3 * NSTORE) { seg = 2; node = gw - 2 * NSTORE; }
    else return;

    const int* off = &g_off[seg * (NSTORE + 1)];
    int start = off[node], end = off[node + 1];
    const int* lst = (seg == 0) ? g_csr_fwd : (seg == 1) ? g_csr_rev : g_csr_rs;
    const float* feat = (seg == 2) ? g_hr : g_hs;

    float ax = 0.f, ay = 0.f, bx = 0.f, by = 0.f;
    int e = start;
    for (; e + 1 < end; e += 2) {
        int n0 = __ldg(&lst[e]);
        int n1 = __ldg(&lst[e + 1]);
        float2 v0 = *(const float2*)&feat[n0 * H + lane * 2];
        float2 v1 = *(const float2*)&feat[n1 * H + lane * 2];
        ax += v0.x; ay += v0.y;
        bx += v1.x; by += v1.y;
    }
    if (e < end) {
        int n0 = __ldg(&lst[e]);
        float2 v0 = *(const float2*)&feat[n0 * H + lane * 2];
        ax += v0.x; ay += v0.y;
    }
    ax += bx; ay += by;
    float inv = (end > start) ? __fdividef(1.f, (float)(end - start)) : 0.f;
    float* out = (seg == 0) ? g_afwd : (seg == 1) ? g_arev : g_ars;
    *(float2*)&out[node * H + lane * 2] = make_float2(ax * inv, ay * inv);
}

// ---------------- mma.sync LSTM (round-9 body, shared-rcp per-cell epilogue) ----------------
#define LS_M 80
#define LS_THREADS 256
#define LS_BLOCKS_S (NSTORE / LS_M)   // 250
#define LS_BLOCKS_R (NREG / LS_M)     // 25

#define OFF_WFRAG 0                   // 16384 u32 = 64 KB
#define OFF_HHI   65536               // 80 x 72 bf16 = 11520 B
#define OFF_HLO   (OFF_HHI + 11520)
#define OFF_XT    (OFF_HLO + 11520)   // 24 x 80 f32
#define OFF_WIN   (OFF_XT + 7680)
#define OFF_BG    (OFF_WIN + 1024)
#define LS_SMEM   (OFF_BG + 1024)     // 98304 B

__global__ __launch_bounds__(LS_THREADS, 2)
void lstm_mma_kernel(const float* __restrict__ x_s, const float* __restrict__ x_r,
                     const float* __restrict__ Wih_s, const float* __restrict__ Whh_s,
                     const float* __restrict__ bih_s, const float* __restrict__ bhh_s,
                     const float* __restrict__ Wih_r, const float* __restrict__ Whh_r,
                     const float* __restrict__ bih_r, const float* __restrict__ bhh_r)
{
    extern __shared__ char smem[];
    uint32_t* Wfrag = (uint32_t*)(smem + OFF_WFRAG);
    __nv_bfloat16* hHi = (__nv_bfloat16*)(smem + OFF_HHI);
    __nv_bfloat16* hLo = (__nv_bfloat16*)(smem + OFF_HLO);
    float* xT   = (float*)(smem + OFF_XT);
    float* winG = (float*)(smem + OFF_WIN);
    float* bG   = (float*)(smem + OFF_BG);

    const int tid = threadIdx.x;
    const bool is_store = (blockIdx.x < LS_BLOCKS_S);
    const int lb = is_store ? blockIdx.x : (blockIdx.x - LS_BLOCKS_S);
    const float* x   = is_store ? x_s   : x_r;
    const float* Wih = is_store ? Wih_s : Wih_r;
    const float* Whh = is_store ? Whh_s : Whh_r;
    const float* bih = is_store ? bih_s : bih_r;
    const float* bhh = is_store ? bhh_s : bhh_r;
    float* hout = is_store ? g_hs : g_hr;
    const int s0 = lb * LS_M;

    // ---- build W fragments (b-frag order) ----
    for (int idx = tid; idx < 16384; idx += LS_THREADS) {
        int ln   = idx & 31;
        int reg  = (idx >> 5) & 1;
        int nt   = (idx >> 6) & 15;
        int ks   = (idx >> 10) & 3;
        int hl   = (idx >> 12) & 1;
        int half = (idx >> 13) & 1;
        int tgi = ln & 3, gidi = ln >> 2;
        int gate = (nt & 1) * 2 + (gidi & 1);
        int unit = half * 32 + (nt >> 1) * 4 + (gidi >> 1);
        int row = gate * 64 + unit;
        int k = ks * 16 + tgi * 2 + reg * 8;
        float w0 = Whh[row * 64 + k];
        float w1 = Whh[row * 64 + k + 1];
        __nv_bfloat16 h0 = __float2bfloat16(w0);
        __nv_bfloat16 h1 = __float2bfloat16(w1);
        uint32_t val;
        if (hl == 0) {
            val = (uint32_t)__bfloat16_as_ushort(h0)
                | ((uint32_t)__bfloat16_as_ushort(h1) << 16);
        } else {
            __nv_bfloat16 l0 = __float2bfloat16(w0 - __bfloat162float(h0));
            __nv_bfloat16 l1 = __float2bfloat16(w1 - __bfloat162float(h1));
            val = (uint32_t)__bfloat16_as_ushort(l0)
                | ((uint32_t)__bfloat16_as_ushort(l1) << 16);
        }
        Wfrag[idx] = val;
    }
    if (tid < 256) {
        int half = tid >> 7, rr = tid & 127;
        int nt = (rr >> 3) & 15, g8 = rr & 7;
        int gate = (nt & 1) * 2 + (g8 & 1);
        int unit = half * 32 + (nt >> 1) * 4 + (g8 >> 1);
        winG[tid] = Wih[gate * 64 + unit];
        bG[tid]   = bih[gate * 64 + unit] + bhh[gate * 64 + unit];
    }
    for (int i = tid; i < 23040 / 4; i += LS_THREADS)
        ((uint32_t*)(smem + OFF_HHI))[i] = 0;
    for (int i = tid; i < LS_M * TS; i += LS_THREADS) {
        int s = i / TS, t = i % TS;
        xT[t * LS_M + s] = x[(s0 + s) * TS + t];
    }
    __syncthreads();

    const int warp = tid >> 5, lane = tid & 31;
    const int tg = lane & 3, gid = lane >> 2;

    float cst[2][10];
#pragma unroll
    for (int i = 0; i < 10; i++) { cst[0][i] = 0.f; cst[1][i] = 0.f; }

    for (int t = 0; t < TS; t++) {
        float hn[2][10];
#pragma unroll
        for (int half = 0; half < 2; half++) {
            float acc[5][2][4];
            // init acc = x*win + b
#pragma unroll
            for (int t01 = 0; t01 < 2; t01++) {
                int r0 = half * 128 + (2 * warp + t01) * 8 + 2 * tg;
                float w0 = winG[r0], w1 = winG[r0 + 1];
                float bb0 = bG[r0], bb1 = bG[r0 + 1];
#pragma unroll
                for (int mt = 0; mt < 5; mt++) {
                    float xa = xT[t * LS_M + mt * 16 + gid];
                    float xb = xT[t * LS_M + mt * 16 + gid + 8];
                    acc[mt][t01][0] = fmaf(xa, w0, bb0);
                    acc[mt][t01][1] = fmaf(xa, w1, bb1);
                    acc[mt][t01][2] = fmaf(xb, w0, bb0);
                    acc[mt][t01][3] = fmaf(xb, w1, bb1);
                }
            }
            // k loop: 4 steps of k16
#pragma unroll
            for (int ks = 0; ks < 4; ks++) {
                const int kb = (ks * 16 + 2 * tg) * 2;   // byte offset of k-pair
                uint32_t a[5][4];
#pragma unroll
                for (int mt = 0; mt < 5; mt++) {
                    int ra = (mt * 16 + gid) * 144;
                    a[mt][0] = *(const uint32_t*)(smem + OFF_HHI + ra + kb);
                    a[mt][1] = *(const uint32_t*)(smem + OFF_HHI + ra + 8 * 144 + kb);
                    a[mt][2] = *(const uint32_t*)(smem + OFF_HHI + ra + kb + 16);
                    a[mt][3] = *(const uint32_t*)(smem + OFF_HHI + ra + 8 * 144 + kb + 16);
                }
                uint32_t bhi[2][2], blo[2][2];
#pragma unroll
                for (int t01 = 0; t01 < 2; t01++) {
                    int nt = 2 * warp + t01;
                    int ih = ((((half * 2 + 0) * 4 + ks) * 16 + nt) * 2) * 32 + lane;
                    int il = ((((half * 2 + 1) * 4 + ks) * 16 + nt) * 2) * 32 + lane;
                    bhi[t01][0] = Wfrag[ih];
                    bhi[t01][1] = Wfrag[ih + 32];
                    blo[t01][0] = Wfrag[il];
                    blo[t01][1] = Wfrag[il + 32];
                }
                // terms: Ahi*Whi + Ahi*Wlo
#pragma unroll
                for (int mt = 0; mt < 5; mt++) {
                    MMA_BF16(acc[mt][0], a[mt], bhi[0]);
                    MMA_BF16(acc[mt][1], a[mt], bhi[1]);
                    MMA_BF16(acc[mt][0], a[mt], blo[0]);
                    MMA_BF16(acc[mt][1], a[mt], blo[1]);
                }
                // term: Alo*Whi
#pragma unroll
                for (int mt = 0; mt < 5; mt++) {
                    int ra = (mt * 16 + gid) * 144;
                    a[mt][0] = *(const uint32_t*)(smem + OFF_HLO + ra + kb);
                    a[mt][1] = *(const uint32_t*)(smem + OFF_HLO + ra + 8 * 144 + kb);
                    a[mt][2] = *(const uint32_t*)(smem + OFF_HLO + ra + kb + 16);
                    a[mt][3] = *(const uint32_t*)(smem + OFF_HLO + ra + 8 * 144 + kb + 16);
                }
#pragma unroll
                for (int mt = 0; mt < 5; mt++) {
                    MMA_BF16(acc[mt][0], a[mt], bhi[0]);
                    MMA_BF16(acc[mt][1], a[mt], bhi[1]);
                }
            }
            // epilogue: per-cell shared reciprocal (exact algebra, small live set)
            // sigma(x) = 1/(1+e^-x); tanh(g) = (1-e^-2g)/(1+e^-2g)
            // r = rcp(d_i d_f d_o d_g); recover each 1/d via prefix products.
#pragma unroll
            for (int mt = 0; mt < 5; mt++) {
#pragma unroll
                for (int sb = 0; sb < 2; sb++) {
                    float gi = acc[mt][0][sb * 2 + 0];
                    float gf = acc[mt][0][sb * 2 + 1];
                    float gg = acc[mt][1][sb * 2 + 0];
                    float go = acc[mt][1][sb * 2 + 1];
                    float ei = __expf(-gi), ef = __expf(-gf);
                    float eo = __expf(-go), eg = __expf(-2.f * gg);
                    float di = 1.f + ei, df = 1.f + ef;
                    float dof = 1.f + eo, dg = 1.f + eg;
                    float p1 = di * df, p2 = dof * dg;
                    float r = rcpf(p1 * p2);
                    float rp2 = r * p2, rp1 = r * p1;
                    float si = rp2 * df;            // 1/di
                    float sf = rp2 * di;            // 1/df
                    float so = rp1 * dg;            // 1/do
                    float tgh = (1.f - eg) * (rp1 * dof);  // tanh(gg)
                    float cc = fmaf(sf, cst[half][mt * 2 + sb], si * tgh);
                    cst[half][mt * 2 + sb] = cc;
                    float ec = __expf(-2.f * cc);
                    hn[half][mt * 2 + sb] = so * (1.f - ec) * rcpf(1.f + ec);
                }
            }
        }
        __syncthreads();   // all GEMM reads of old h done
#pragma unroll
        for (int half = 0; half < 2; half++) {
            int u = half * 32 + warp * 4 + tg;
#pragma unroll
            for (int mt = 0; mt < 5; mt++) {
#pragma unroll
                for (int sb = 0; sb < 2; sb++) {
                    int s = mt * 16 + gid + sb * 8;
                    float h = hn[half][mt * 2 + sb];
                    __nv_bfloat16 hh = __float2bfloat16(h);
                    __nv_bfloat16 hl = __float2bfloat16(h - __bfloat162float(hh));
                    hHi[s * 72 + u] = hh;
                    hLo[s * 72 + u] = hl;
                    if (t == TS - 1) hout[(s0 + s) * H + u] = h;
                }
            }
        }
        __syncthreads();   // new h visible for t+1
    }
}

// ---------------- fused finalize ----------------
#define FIN_NODES 16
#define FIN_THREADS 1024
#define FIN_WS 65
#define FIN_SMEM_FLOATS (5 * H * FIN_WS + FIN_NODES * 4 * H + FIN_NODES * H + 2 * H)

__global__ __launch_bounds__(FIN_THREADS, 1)
void finalize_kernel(const float* __restrict__ W_s2d, const float* __restrict__ b_s2d,
                     const float* __restrict__ W_d2s, const float* __restrict__ b_d2s,
                     const float* __restrict__ W_self, const float* __restrict__ b_self,
                     const float* __restrict__ Wl_rs, const float* __restrict__ bl_rs,
                     const float* __restrict__ Wr_rs,
                     const float* __restrict__ Wf, const float* __restrict__ bf,
                     float* __restrict__ out)
{
    extern __shared__ float smemf[];
    float* Wsum = smemf;
    float* Wa   = Wsum + H * FIN_WS;
    float* Wb   = Wa + H * FIN_WS;
    float* Wc   = Wb + H * FIN_WS;
    float* Wfo  = Wc + H * FIN_WS;
    float* vec  = Wfo + H * FIN_WS;
    float* shm  = vec + FIN_NODES * 4 * H;
    float* btot = shm + FIN_NODES * H;
    float* bfv  = btot + H;

    const int tid = threadIdx.x;
    const int n0 = blockIdx.x * FIN_NODES;

    for (int i = tid; i < H * H; i += FIN_THREADS) {
        int r = i >> 6, cix = i & 63;
        Wsum[r * FIN_WS + cix] = W_self[i] + Wr_rs[i];
        Wa[r * FIN_WS + cix]   = W_s2d[i];
        Wb[r * FIN_WS + cix]   = W_d2s[i];
        Wc[r * FIN_WS + cix]   = Wl_rs[i];
        Wfo[r * FIN_WS + cix]  = Wf[i];
    }
    if (tid < H) {
        btot[tid] = b_self[tid] + bl_rs[tid]
                  + (1.f - ALPHA) * b_s2d[tid] + ALPHA * b_d2s[tid];
        bfv[tid] = bf[tid];
    }
    for (int i = tid; i < FIN_NODES * 4 * H; i += FIN_THREADS) {
        int n = i >> 8, v = (i >> 6) & 3, k = i & 63;
        int node = n0 + n;
        float val = 0.f;
        if (node < NSTORE) {
            if (v == 0)      val = g_hs[node * H + k];
            else if (v == 1) val = (1.f - ALPHA) * g_afwd[node * H + k];
            else if (v == 2) val = ALPHA * g_arev[node * H + k];
            else             val = g_ars[node * H + k];
        }
        vec[i] = val;
    }
    __syncthreads();

    const int n = tid >> 6, u = tid & 63;
    const float* v0 = &vec[(n * 4 + 0) * H];
    const float* v1 = &vec[(n * 4 + 1) * H];
    const float* v2 = &vec[(n * 4 + 2) * H];
    const float* v3 = &vec[(n * 4 + 3) * H];

    float acc = btot[u];
#pragma unroll 8
    for (int k = 0; k < H; k++) {
        acc = fmaf(v0[k], Wsum[u * FIN_WS + k], acc);
        acc = fmaf(v1[k], Wa[u * FIN_WS + k], acc);
        acc = fmaf(v2[k], Wb[u * FIN_WS + k], acc);
        acc = fmaf(v3[k], Wc[u * FIN_WS + k], acc);
    }
    float sh = fmaxf(0.f, v0[u] + 0.5f * acc);
    shm[n * H + u] = sh;
    __syncthreads();

    float acc2 = bfv[u];
#pragma unroll 8
    for (int k = 0; k < H; k++)
        acc2 = fmaf(Wfo[u * FIN_WS + k], shm[n * H + k], acc2);

    int node = n0 + n;
    if (node < NSTORE) out[node * H + u] = acc2;
}

// ---------------- launch ----------------
extern "C" void kernel_launch(void* const* d_in, const int* in_sizes, int n_in,
                              void* d_out, int out_size)
{
    const float* x_store  = (const float*)d_in[0];
    const float* x_region = (const float*)d_in[1];
    const int* ess    = (const int*)d_in[2];
    const int* rs_src = (const int*)d_in[3];
    const int* rs_dst = (const int*)d_in[4];
    const float* Wih_s = (const float*)d_in[7];
    const float* Whh_s = (const float*)d_in[8];
    const float* bih_s = (const float*)d_in[9];
    const float* bhh_s = (const float*)d_in[10];
    const float* Wih_r = (const float*)d_in[11];
    const float* Whh_r = (const float*)d_in[12];
    const float* bih_r = (const float*)d_in[13];
    const float* bhh_r = (const float*)d_in[14];
    const float* W_s2d = (const float*)d_in[15];
    const float* b_s2d = (const float*)d_in[16];
    const float* W_d2s = (const float*)d_in[17];
    const float* b_d2s = (const float*)d_in[18];
    const float* W_self = (const float*)d_in[19];
    const float* b_self = (const float*)d_in[20];
    const float* Wl_rs = (const float*)d_in[21];
    const float* bl_rs = (const float*)d_in[22];
    const float* Wr_rs = (const float*)d_in[23];
    const float* Wf = (const float*)d_in[27];
    const float* bf = (const float*)d_in[28];

    static cudaStream_t s_side = nullptr;
    static cudaEvent_t ev_fork = nullptr, ev_join = nullptr;
    if (!s_side) {
        cudaStreamCreateWithFlags(&s_side, cudaStreamNonBlocking);
        cudaEventCreateWithFlags(&ev_fork, cudaEventDisableTiming);
        cudaEventCreateWithFlags(&ev_join, cudaEventDisableTiming);
    }

    const size_t fin_smem = FIN_SMEM_FLOATS * sizeof(float);
    cudaFuncSetAttribute(lstm_mma_kernel, cudaFuncAttributeMaxDynamicSharedMemorySize, LS_SMEM);
    cudaFuncSetAttribute(finalize_kernel, cudaFuncAttributeMaxDynamicSharedMemorySize, (int)fin_smem);

    // Fork: CSR build on side stream, LSTM on main stream.
    cudaEventRecord(ev_fork, 0);
    cudaStreamWaitEvent(s_side, ev_fork, 0);

    zero_cnt_kernel<<<(3 * NSTORE + 255) / 256, 256, 0, s_side>>>();
    count_kernel<<<(E_SS + 255) / 256, 256, 0, s_side>>>(ess, ess + E_SS, rs_dst);
    scan_kernel<<<3, 1024, 0, s_side>>>();

    lstm_mma_kernel<<<LS_BLOCKS_S + LS_BLOCKS_R, LS_THREADS, LS_SMEM>>>(
        x_store, x_region,
        Wih_s, Whh_s, bih_s, bhh_s,
        Wih_r, Whh_r, bih_r, bhh_r);

    scatter_kernel<<<(E_SS + 255) / 256, 256, 0, s_side>>>(ess, ess + E_SS, rs_src, rs_dst);

    cudaEventRecord(ev_join, s_side);
    cudaStreamWaitEvent(0, ev_join, 0);

    gather_kernel<<<(3 * NSTORE + GATHER_WARPS - 1) / GATHER_WARPS, 256>>>();

    finalize_kernel<<<(NSTORE + FIN_NODES - 1) / FIN_NODES, FIN_THREADS, fin_smem>>>(
        W_s2d, b_s2d, W_d2s, b_d2s, W_self, b_self,
        Wl_rs, bl_rs, Wr_rs, Wf, bf, (float*)d_out);
}

// round 12
// speedup vs baseline: 1.3877x; 1.0809x over previous
#include <cuda_runtime.h>
#include <cuda_bf16.h>
#include <cstdint>

#define H 64
#define TS 24
#define NSTORE 20000
#define NREG 2000
#define E_SS 640000
#define E_RS 160000
#define ALPHA 0.5f

// ---------------- device scratch ----------------
__device__ float g_hs[NSTORE * H];
__device__ float g_hr[NREG * H];
__device__ float g_afwd[NSTORE * H];
__device__ float g_arev[NSTORE * H];
__device__ float g_ars[NSTORE * H];
__device__ int g_cnt[3 * NSTORE];
__device__ int g_off[3 * (NSTORE + 1)];
__device__ int g_cur[3 * NSTORE];
__device__ int g_csr_fwd[E_SS];
__device__ int g_csr_rev[E_SS];
__device__ int g_csr_rs[E_RS];

// ---------------- activations (round-9 proven) ----------------
__device__ __forceinline__ float sigf(float x) {
    return __fdividef(1.f, 1.f + __expf(-x));
}
__device__ __forceinline__ float tanh_fast(float x) {
    float e = __expf(-2.f * x);
    return __fdividef(1.f - e, 1.f + e);
}

// bf16 mma (base PTX, sm_80+; HMMA pipe)
#define MMA_BF16(d, a, b) \
    asm volatile("mma.sync.aligned.m16n8k16.row.col.f32.bf16.bf16.f32 " \
        "{%0,%1,%2,%3}, {%4,%5,%6,%7}, {%8,%9}, {%0,%1,%2,%3};" \
        : "+f"((d)[0]), "+f"((d)[1]), "+f"((d)[2]), "+f"((d)[3]) \
        : "r"((a)[0]), "r"((a)[1]), "r"((a)[2]), "r"((a)[3]), \
          "r"((b)[0]), "r"((b)[1]))

__device__ __forceinline__ void ldsm_x4(uint32_t* r, uint32_t addr) {
    asm volatile("ldmatrix.sync.aligned.m8n8.x4.shared.b16 {%0,%1,%2,%3}, [%4];"
        : "=r"(r[0]), "=r"(r[1]), "=r"(r[2]), "=r"(r[3]) : "r"(addr));
}

// ---------------- CSR build ----------------
__global__ void zero_cnt_kernel() {
    int i = blockIdx.x * blockDim.x + threadIdx.x;
    if (i < 3 * NSTORE) g_cnt[i] = 0;
}

__global__ void count_kernel(const int* __restrict__ src, const int* __restrict__ dst,
                             const int* __restrict__ rs_dst) {
    int e = blockIdx.x * blockDim.x + threadIdx.x;
    if (e < E_SS) {
        atomicAdd(&g_cnt[dst[e]], 1);
        atomicAdd(&g_cnt[NSTORE + src[e]], 1);
    }
    if (e < E_RS) atomicAdd(&g_cnt[2 * NSTORE + rs_dst[e]], 1);
}

// One-pass scan: 1024 threads x 20 items/thread (20480 >= 20000).
__global__ void scan_kernel() {
    __shared__ int ssum[1024];
    const int seg = blockIdx.x;
    const int base = seg * NSTORE;
    const int tid = threadIdx.x;
    const int start = tid * 20;
    int local[20];
    int sum = 0;
#pragma unroll
    for (int j = 0; j < 20; j++) {
        int i = start + j;
        int v = (i < NSTORE) ? g_cnt[base + i] : 0;
        local[j] = sum;
        sum += v;
    }
    ssum[tid] = sum;
    __syncthreads();
    for (int ofs = 1; ofs < 1024; ofs <<= 1) {
        int y = (tid >= ofs) ? ssum[tid - ofs] : 0;
        __syncthreads();
        ssum[tid] += y;
        __syncthreads();
    }
    int excl = (tid > 0) ? ssum[tid - 1] : 0;
#pragma unroll
    for (int j = 0; j < 20; j++) {
        int i = start + j;
        if (i < NSTORE) {
            int e = excl + local[j];
            g_off[seg * (NSTORE + 1) + i] = e;
            g_cur[base + i] = e;
        }
    }
    if (tid == 1023) g_off[seg * (NSTORE + 1) + NSTORE] = ssum[1023];
}

__global__ void scatter_kernel(const int* __restrict__ src, const int* __restrict__ dst,
                               const int* __restrict__ rs_src, const int* __restrict__ rs_dst) {
    int e = blockIdx.x * blockDim.x + threadIdx.x;
    if (e < E_SS) {
        int s = src[e], d = dst[e];
        g_csr_fwd[atomicAdd(&g_cur[d], 1)] = s;
        g_csr_rev[atomicAdd(&g_cur[NSTORE + s], 1)] = d;
    }
    if (e < E_RS) {
        g_csr_rs[atomicAdd(&g_cur[2 * NSTORE + rs_dst[e]], 1)] = rs_src[e];
    }
}

// ---------------- gather (mean), 2-edge unrolled ----------------
#define GATHER_WARPS 8
__global__ __launch_bounds__(256)
void gather_kernel() {
    int gw = blockIdx.x * GATHER_WARPS + (threadIdx.x >> 5);
    int lane = threadIdx.x & 31;
    int seg, node;
    if (gw < NSTORE)          { seg = 0; node = gw; }
    else if (gw < 2 * NSTORE) { seg = 1; node = gw - NSTORE; }
    else if (gw < 3 * NSTORE) { seg = 2; node = gw - 2 * NSTORE; }
    else return;

    const int* off = &g_off[seg * (NSTORE + 1)];
    int start = off[node], end = off[node + 1];
    const int* lst = (seg == 0) ? g_csr_fwd : (seg == 1) ? g_csr_rev : g_csr_rs;
    const float* feat = (seg == 2) ? g_hr : g_hs;

    float ax = 0.f, ay = 0.f, bx = 0.f, by = 0.f;
    int e = start;
    for (; e + 1 < end; e += 2) {
        int n0 = __ldg(&lst[e]);
        int n1 = __ldg(&lst[e + 1]);
        float2 v0 = *(const float2*)&feat[n0 * H + lane * 2];
        float2 v1 = *(const float2*)&feat[n1 * H + lane * 2];
        ax += v0.x; ay += v0.y;
        bx += v1.x; by += v1.y;
    }
    if (e < end) {
        int n0 = __ldg(&lst[e]);
        float2 v0 = *(const float2*)&feat[n0 * H + lane * 2];
        ax += v0.x; ay += v0.y;
    }
    ax += bx; ay += by;
    float inv = (end > start) ? __fdividef(1.f, (float)(end - start)) : 0.f;
    float* out = (seg == 0) ? g_afwd : (seg == 1) ? g_arev : g_ars;
    *(float2*)&out[node * H + lane * 2] = make_float2(ax * inv, ay * inv);
}

// ---------------- mma.sync LSTM: round-9 body + ldmatrix A-loads ----------------
#define LS_M 80
#define LS_THREADS 256
#define LS_BLOCKS_S (NSTORE / LS_M)   // 250
#define LS_BLOCKS_R (NREG / LS_M)     // 25

#define OFF_WFRAG 0                   // 16384 u32 = 64 KB
#define OFF_HHI   65536               // 80 x 72 bf16 = 11520 B
#define OFF_HLO   (OFF_HHI + 11520)
#define OFF_XT    (OFF_HLO + 11520)   // 24 x 80 f32
#define OFF_WIN   (OFF_XT + 7680)
#define OFF_BG    (OFF_WIN + 1024)
#define LS_SMEM   (OFF_BG + 1024)     // 98304 B

__global__ __launch_bounds__(LS_THREADS, 2)
void lstm_mma_kernel(const float* __restrict__ x_s, const float* __restrict__ x_r,
                     const float* __restrict__ Wih_s, const float* __restrict__ Whh_s,
                     const float* __restrict__ bih_s, const float* __restrict__ bhh_s,
                     const float* __restrict__ Wih_r, const float* __restrict__ Whh_r,
                     const float* __restrict__ bih_r, const float* __restrict__ bhh_r)
{
    extern __shared__ char smem[];
    uint32_t* Wfrag = (uint32_t*)(smem + OFF_WFRAG);
    __nv_bfloat16* hHi = (__nv_bfloat16*)(smem + OFF_HHI);
    __nv_bfloat16* hLo = (__nv_bfloat16*)(smem + OFF_HLO);
    float* xT   = (float*)(smem + OFF_XT);
    float* winG = (float*)(smem + OFF_WIN);
    float* bG   = (float*)(smem + OFF_BG);

    const int tid = threadIdx.x;
    const bool is_store = (blockIdx.x < LS_BLOCKS_S);
    const int lb = is_store ? blockIdx.x : (blockIdx.x - LS_BLOCKS_S);
    const float* x   = is_store ? x_s   : x_r;
    const float* Wih = is_store ? Wih_s : Wih_r;
    const float* Whh = is_store ? Whh_s : Whh_r;
    const float* bih = is_store ? bih_s : bih_r;
    const float* bhh = is_store ? bhh_s : bhh_r;
    float* hout = is_store ? g_hs : g_hr;
    const int s0 = lb * LS_M;

    // ---- build W fragments (b-frag order) ----
    for (int idx = tid; idx < 16384; idx += LS_THREADS) {
        int ln   = idx & 31;
        int reg  = (idx >> 5) & 1;
        int nt   = (idx >> 6) & 15;
        int ks   = (idx >> 10) & 3;
        int hl   = (idx >> 12) & 1;
        int half = (idx >> 13) & 1;
        int tgi = ln & 3, gidi = ln >> 2;
        int gate = (nt & 1) * 2 + (gidi & 1);
        int unit = half * 32 + (nt >> 1) * 4 + (gidi >> 1);
        int row = gate * 64 + unit;
        int k = ks * 16 + tgi * 2 + reg * 8;
        float w0 = Whh[row * 64 + k];
        float w1 = Whh[row * 64 + k + 1];
        __nv_bfloat16 h0 = __float2bfloat16(w0);
        __nv_bfloat16 h1 = __float2bfloat16(w1);
        uint32_t val;
        if (hl == 0) {
            val = (uint32_t)__bfloat16_as_ushort(h0)
                | ((uint32_t)__bfloat16_as_ushort(h1) << 16);
        } else {
            __nv_bfloat16 l0 = __float2bfloat16(w0 - __bfloat162float(h0));
            __nv_bfloat16 l1 = __float2bfloat16(w1 - __bfloat162float(h1));
            val = (uint32_t)__bfloat16_as_ushort(l0)
                | ((uint32_t)__bfloat16_as_ushort(l1) << 16);
        }
        Wfrag[idx] = val;
    }
    if (tid < 256) {
        int half = tid >> 7, rr = tid & 127;
        int nt = (rr >> 3) & 15, g8 = rr & 7;
        int gate = (nt & 1) * 2 + (g8 & 1);
        int unit = half * 32 + (nt >> 1) * 4 + (g8 >> 1);
        winG[tid] = Wih[gate * 64 + unit];
        bG[tid]   = bih[gate * 64 + unit] + bhh[gate * 64 + unit];
    }
    for (int i = tid; i < 23040 / 4; i += LS_THREADS)
        ((uint32_t*)(smem + OFF_HHI))[i] = 0;
    for (int i = tid; i < LS_M * TS; i += LS_THREADS) {
        int s = i / TS, t = i % TS;
        xT[t * LS_M + s] = x[(s0 + s) * TS + t];
    }
    __syncthreads();

    const int warp = tid >> 5, lane = tid & 31;
    const int tg = lane & 3, gid = lane >> 2;

    // ldmatrix per-lane base: mat = lane>>3 (0..3), r8 = lane&7
    // mat0=(r,k0) mat1=(r+8,k0) mat2=(r,k8) mat3=(r+8,k8); row stride 144 B.
    const int mat = lane >> 3, r8 = lane & 7;
    const uint32_t sbase32 = (uint32_t)__cvta_generic_to_shared(smem);
    const uint32_t aoff = (uint32_t)(((mat & 1) * 8 + r8) * 144 + (mat >> 1) * 16);
    const uint32_t aHiB = sbase32 + OFF_HHI + aoff;
    const uint32_t aLoB = sbase32 + OFF_HLO + aoff;

    float cst[2][10];
#pragma unroll
    for (int i = 0; i < 10; i++) { cst[0][i] = 0.f; cst[1][i] = 0.f; }

    for (int t = 0; t < TS; t++) {
        float hn[2][10];
#pragma unroll
        for (int half = 0; half < 2; half++) {
            float acc[5][2][4];
            // init acc = x*win + b (x loaded inline per half, round-9 style)
#pragma unroll
            for (int t01 = 0; t01 < 2; t01++) {
                int r0 = half * 128 + (2 * warp + t01) * 8 + 2 * tg;
                float w0 = winG[r0], w1 = winG[r0 + 1];
                float bb0 = bG[r0], bb1 = bG[r0 + 1];
#pragma unroll
                for (int mt = 0; mt < 5; mt++) {
                    float xa = xT[t * LS_M + mt * 16 + gid];
                    float xb = xT[t * LS_M + mt * 16 + gid + 8];
                    acc[mt][t01][0] = fmaf(xa, w0, bb0);
                    acc[mt][t01][1] = fmaf(xa, w1, bb1);
                    acc[mt][t01][2] = fmaf(xb, w0, bb0);
                    acc[mt][t01][3] = fmaf(xb, w1, bb1);
                }
            }
            // k loop: 4 steps of k16
#pragma unroll
            for (int ks = 0; ks < 4; ks++) {
                uint32_t a[5][4];
#pragma unroll
                for (int mt = 0; mt < 5; mt++)
                    ldsm_x4(a[mt], aHiB + mt * 2304 + ks * 32);
                uint32_t bhi[2][2], blo[2][2];
#pragma unroll
                for (int t01 = 0; t01 < 2; t01++) {
                    int nt = 2 * warp + t01;
                    int ih = ((((half * 2 + 0) * 4 + ks) * 16 + nt) * 2) * 32 + lane;
                    int il = ((((half * 2 + 1) * 4 + ks) * 16 + nt) * 2) * 32 + lane;
                    bhi[t01][0] = Wfrag[ih];
                    bhi[t01][1] = Wfrag[ih + 32];
                    blo[t01][0] = Wfrag[il];
                    blo[t01][1] = Wfrag[il + 32];
                }
                // terms: Ahi*Whi + Ahi*Wlo
#pragma unroll
                for (int mt = 0; mt < 5; mt++) {
                    MMA_BF16(acc[mt][0], a[mt], bhi[0]);
                    MMA_BF16(acc[mt][1], a[mt], bhi[1]);
                    MMA_BF16(acc[mt][0], a[mt], blo[0]);
                    MMA_BF16(acc[mt][1], a[mt], blo[1]);
                }
                // term: Alo*Whi
#pragma unroll
                for (int mt = 0; mt < 5; mt++)
                    ldsm_x4(a[mt], aLoB + mt * 2304 + ks * 32);
#pragma unroll
                for (int mt = 0; mt < 5; mt++) {
                    MMA_BF16(acc[mt][0], a[mt], bhi[0]);
                    MMA_BF16(acc[mt][1], a[mt], bhi[1]);
                }
            }
            // epilogue: round-9 plain activations (proven fastest)
#pragma unroll
            for (int mt = 0; mt < 5; mt++) {
#pragma unroll
                for (int sb = 0; sb < 2; sb++) {
                    float gi = acc[mt][0][sb * 2 + 0];
                    float gf = acc[mt][0][sb * 2 + 1];
                    float gg = acc[mt][1][sb * 2 + 0];
                    float go = acc[mt][1][sb * 2 + 1];
                    float cc = cst[half][mt * 2 + sb];
                    cc = sigf(gf) * cc + sigf(gi) * tanh_fast(gg);
                    cst[half][mt * 2 + sb] = cc;
                    hn[half][mt * 2 + sb] = sigf(go) * tanh_fast(cc);
                }
            }
        }
        __syncthreads();   // all GEMM reads of old h done
#pragma unroll
        for (int half = 0; half < 2; half++) {
            int u = half * 32 + warp * 4 + tg;
#pragma unroll
            for (int mt = 0; mt < 5; mt++) {
#pragma unroll
                for (int sb = 0; sb < 2; sb++) {
                    int s = mt * 16 + gid + sb * 8;
                    float h = hn[half][mt * 2 + sb];
                    __nv_bfloat16 hh = __float2bfloat16(h);
                    __nv_bfloat16 hl = __float2bfloat16(h - __bfloat162float(hh));
                    hHi[s * 72 + u] = hh;
                    hLo[s * 72 + u] = hl;
                    if (t == TS - 1) hout[(s0 + s) * H + u] = h;
                }
            }
        }
        __syncthreads();   // new h visible for t+1
    }
}

// ---------------- fused finalize ----------------
#define FIN_NODES 16
#define FIN_THREADS 1024
#define FIN_WS 65
#define FIN_SMEM_FLOATS (5 * H * FIN_WS + FIN_NODES * 4 * H + FIN_NODES * H + 2 * H)

__global__ __launch_bounds__(FIN_THREADS, 1)
void finalize_kernel(const float* __restrict__ W_s2d, const float* __restrict__ b_s2d,
                     const float* __restrict__ W_d2s, const float* __restrict__ b_d2s,
                     const float* __restrict__ W_self, const float* __restrict__ b_self,
                     const float* __restrict__ Wl_rs, const float* __restrict__ bl_rs,
                     const float* __restrict__ Wr_rs,
                     const float* __restrict__ Wf, const float* __restrict__ bf,
                     float* __restrict__ out)
{
    extern __shared__ float smemf[];
    float* Wsum = smemf;
    float* Wa   = Wsum + H * FIN_WS;
    float* Wb   = Wa + H * FIN_WS;
    float* Wc   = Wb + H * FIN_WS;
    float* Wfo  = Wc + H * FIN_WS;
    float* vec  = Wfo + H * FIN_WS;
    float* shm  = vec + FIN_NODES * 4 * H;
    float* btot = shm + FIN_NODES * H;
    float* bfv  = btot + H;

    const int tid = threadIdx.x;
    const int n0 = blockIdx.x * FIN_NODES;

    for (int i = tid; i < H * H; i += FIN_THREADS) {
        int r = i >> 6, cix = i & 63;
        Wsum[r * FIN_WS + cix] = W_self[i] + Wr_rs[i];
        Wa[r * FIN_WS + cix]   = W_s2d[i];
        Wb[r * FIN_WS + cix]   = W_d2s[i];
        Wc[r * FIN_WS + cix]   = Wl_rs[i];
        Wfo[r * FIN_WS + cix]  = Wf[i];
    }
    if (tid < H) {
        btot[tid] = b_self[tid] + bl_rs[tid]
                  + (1.f - ALPHA) * b_s2d[tid] + ALPHA * b_d2s[tid];
        bfv[tid] = bf[tid];
    }
    for (int i = tid; i < FIN_NODES * 4 * H; i += FIN_THREADS) {
        int n = i >> 8, v = (i >> 6) & 3, k = i & 63;
        int node = n0 + n;
        float val = 0.f;
        if (node < NSTORE) {
            if (v == 0)      val = g_hs[node * H + k];
            else if (v == 1) val = (1.f - ALPHA) * g_afwd[node * H + k];
            else if (v == 2) val = ALPHA * g_arev[node * H + k];
            else             val = g_ars[node * H + k];
        }
        vec[i] = val;
    }
    __syncthreads();

    const int n = tid >> 6, u = tid & 63;
    const float* v0 = &vec[(n * 4 + 0) * H];
    const float* v1 = &vec[(n * 4 + 1) * H];
    const float* v2 = &vec[(n * 4 + 2) * H];
    const float* v3 = &vec[(n * 4 + 3) * H];

    float acc = btot[u];
#pragma unroll 8
    for (int k = 0; k < H; k++) {
        acc = fmaf(v0[k], Wsum[u * FIN_WS + k], acc);
        acc = fmaf(v1[k], Wa[u * FIN_WS + k], acc);
        acc = fmaf(v2[k], Wb[u * FIN_WS + k], acc);
        acc = fmaf(v3[k], Wc[u * FIN_WS + k], acc);
    }
    float sh = fmaxf(0.f, v0[u] + 0.5f * acc);
    shm[n * H + u] = sh;
    __syncthreads();

    float acc2 = bfv[u];
#pragma unroll 8
    for (int k = 0; k < H; k++)
        acc2 = fmaf(Wfo[u * FIN_WS + k], shm[n * H + k], acc2);

    int node = n0 + n;
    if (node < NSTORE) out[node * H + u] = acc2;
}

// ---------------- launch ----------------
extern "C" void kernel_launch(void* const* d_in, const int* in_sizes, int n_in,
                              void* d_out, int out_size)
{
    const float* x_store  = (const float*)d_in[0];
    const float* x_region = (const float*)d_in[1];
    const int* ess    = (const int*)d_in[2];
    const int* rs_src = (const int*)d_in[3];
    const int* rs_dst = (const int*)d_in[4];
    const float* Wih_s = (const float*)d_in[7];
    const float* Whh_s = (const float*)d_in[8];
    const float* bih_s = (const float*)d_in[9];
    const float* bhh_s = (const float*)d_in[10];
    const float* Wih_r = (const float*)d_in[11];
    const float* Whh_r = (const float*)d_in[12];
    const float* bih_r = (const float*)d_in[13];
    const float* bhh_r = (const float*)d_in[14];
    const float* W_s2d = (const float*)d_in[15];
    const float* b_s2d = (const float*)d_in[16];
    const float* W_d2s = (const float*)d_in[17];
    const float* b_d2s = (const float*)d_in[18];
    const float* W_self = (const float*)d_in[19];
    const float* b_self = (const float*)d_in[20];
    const float* Wl_rs = (const float*)d_in[21];
    const float* bl_rs = (const float*)d_in[22];
    const float* Wr_rs = (const float*)d_in[23];
    const float* Wf = (const float*)d_in[27];
    const float* bf = (const float*)d_in[28];

    static cudaStream_t s_side = nullptr;
    static cudaEvent_t ev_fork = nullptr, ev_join = nullptr;
    if (!s_side) {
        cudaStreamCreateWithFlags(&s_side, cudaStreamNonBlocking);
        cudaEventCreateWithFlags(&ev_fork, cudaEventDisableTiming);
        cudaEventCreateWithFlags(&ev_join, cudaEventDisableTiming);
    }

    const size_t fin_smem = FIN_SMEM_FLOATS * sizeof(float);
    cudaFuncSetAttribute(lstm_mma_kernel, cudaFuncAttributeMaxDynamicSharedMemorySize, LS_SMEM);
    cudaFuncSetAttribute(finalize_kernel, cudaFuncAttributeMaxDynamicSharedMemorySize, (int)fin_smem);

    // Fork: CSR build on side stream, LSTM on main stream.
    cudaEventRecord(ev_fork, 0);
    cudaStreamWaitEvent(s_side, ev_fork, 0);

    zero_cnt_kernel<<<(3 * NSTORE + 255) / 256, 256, 0, s_side>>>();
    count_kernel<<<(E_SS + 255) / 256, 256, 0, s_side>>>(ess, ess + E_SS, rs_dst);
    scan_kernel<<<3, 1024, 0, s_side>>>();

    lstm_mma_kernel<<<LS_BLOCKS_S + LS_BLOCKS_R, LS_THREADS, LS_SMEM>>>(
        x_store, x_region,
        Wih_s, Whh_s, bih_s, bhh_s,
        Wih_r, Whh_r, bih_r, bhh_r);

    scatter_kernel<<<(E_SS + 255) / 256, 256, 0, s_side>>>(ess, ess + E_SS, rs_src, rs_dst);

    cudaEventRecord(ev_join, s_side);
    cudaStreamWaitEvent(0, ev_join, 0);

    gather_kernel<<<(3 * NSTORE + GATHER_WARPS - 1) / GATHER_WARPS, 256>>>();

    finalize_kernel<<<(NSTORE + FIN_NODES - 1) / FIN_NODES, FIN_THREADS, fin_smem>>>(
        W_s2d, b_s2d, W_d2s, b_d2s, W_self, b_self,
        Wl_rs, bl_rs, Wr_rs, Wf, bf, (float*)d_out);
}

// round 13
// speedup vs baseline: 1.4551x; 1.0486x over previous
#include <cuda_runtime.h>
#include <cuda_bf16.h>
#include <cstdint>

#define H 64
#define TS 24
#define NSTORE 20000
#define NREG 2000
#define E_SS 640000
#define E_RS 160000
#define ALPHA 0.5f

// ---------------- device scratch ----------------
__device__ float g_hs[NSTORE * H];
__device__ float g_hr[NREG * H];
__device__ float g_afwd[NSTORE * H];
__device__ float g_arev[NSTORE * H];
__device__ float g_ars[NSTORE * H];
__device__ int g_cnt[3 * NSTORE];
__device__ int g_off[3 * (NSTORE + 1)];
__device__ int g_cur[3 * NSTORE];
__device__ int g_csr_fwd[E_SS];
__device__ int g_csr_rev[E_SS];
__device__ int g_csr_rs[E_RS];

// ---------------- activations ----------------
__device__ __forceinline__ float sigf(float x) {
    return __fdividef(1.f, 1.f + __expf(-x));
}
__device__ __forceinline__ float tanh_fast(float x) {
    float e = __expf(-2.f * x);
    return __fdividef(1.f - e, 1.f + e);
}

// bf16 mma (base PTX, sm_80+; HMMA pipe)
#define MMA_BF16(d, a, b) \
    asm volatile("mma.sync.aligned.m16n8k16.row.col.f32.bf16.bf16.f32 " \
        "{%0,%1,%2,%3}, {%4,%5,%6,%7}, {%8,%9}, {%0,%1,%2,%3};" \
        : "+f"((d)[0]), "+f"((d)[1]), "+f"((d)[2]), "+f"((d)[3]) \
        : "r"((a)[0]), "r"((a)[1]), "r"((a)[2]), "r"((a)[3]), \
          "r"((b)[0]), "r"((b)[1]))

__device__ __forceinline__ void ldsm_x4(uint32_t* r, uint32_t addr) {
    asm volatile("ldmatrix.sync.aligned.m8n8.x4.shared.b16 {%0,%1,%2,%3}, [%4];"
        : "=r"(r[0]), "=r"(r[1]), "=r"(r[2]), "=r"(r[3]) : "r"(addr));
}

// ---------------- CSR build ----------------
__global__ void zero_cnt_kernel() {
    int i = blockIdx.x * blockDim.x + threadIdx.x;
    if (i < 3 * NSTORE) g_cnt[i] = 0;
}

__global__ void count_kernel(const int* __restrict__ src, const int* __restrict__ dst,
                             const int* __restrict__ rs_dst) {
    int e = blockIdx.x * blockDim.x + threadIdx.x;
    if (e < E_SS) {
        atomicAdd(&g_cnt[dst[e]], 1);
        atomicAdd(&g_cnt[NSTORE + src[e]], 1);
    }
    if (e < E_RS) atomicAdd(&g_cnt[2 * NSTORE + rs_dst[e]], 1);
}

// One-pass scan: 1024 threads x 20 items/thread.
__global__ void scan_kernel() {
    __shared__ int ssum[1024];
    const int seg = blockIdx.x;
    const int base = seg * NSTORE;
    const int tid = threadIdx.x;
    const int start = tid * 20;
    int local[20];
    int sum = 0;
#pragma unroll
    for (int j = 0; j < 20; j++) {
        int i = start + j;
        int v = (i < NSTORE) ? g_cnt[base + i] : 0;
        local[j] = sum;
        sum += v;
    }
    ssum[tid] = sum;
    __syncthreads();
    for (int ofs = 1; ofs < 1024; ofs <<= 1) {
        int y = (tid >= ofs) ? ssum[tid - ofs] : 0;
        __syncthreads();
        ssum[tid] += y;
        __syncthreads();
    }
    int excl = (tid > 0) ? ssum[tid - 1] : 0;
#pragma unroll
    for (int j = 0; j < 20; j++) {
        int i = start + j;
        if (i < NSTORE) {
            int e = excl + local[j];
            g_off[seg * (NSTORE + 1) + i] = e;
            g_cur[base + i] = e;
        }
    }
    if (tid == 1023) g_off[seg * (NSTORE + 1) + NSTORE] = ssum[1023];
}

__global__ void scatter_kernel(const int* __restrict__ src, const int* __restrict__ dst,
                               const int* __restrict__ rs_src, const int* __restrict__ rs_dst) {
    int e = blockIdx.x * blockDim.x + threadIdx.x;
    if (e < E_SS) {
        int s = src[e], d = dst[e];
        g_csr_fwd[atomicAdd(&g_cur[d], 1)] = s;
        g_csr_rev[atomicAdd(&g_cur[NSTORE + s], 1)] = d;
    }
    if (e < E_RS) {
        g_csr_rs[atomicAdd(&g_cur[2 * NSTORE + rs_dst[e]], 1)] = rs_src[e];
    }
}

// ---------------- gather (mean), 2-edge unrolled ----------------
#define GATHER_WARPS 8
__global__ __launch_bounds__(256)
void gather_kernel() {
    int gw = blockIdx.x * GATHER_WARPS + (threadIdx.x >> 5);
    int lane = threadIdx.x & 31;
    int seg, node;
    if (gw < NSTORE)          { seg = 0; node = gw; }
    else if (gw < 2 * NSTORE) { seg = 1; node = gw - NSTORE; }
    else if (gw < 3 * NSTORE) { seg = 2; node = gw - 2 * NSTORE; }
    else return;

    const int* off = &g_off[seg * (NSTORE + 1)];
    int start = off[node], end = off[node + 1];
    const int* lst = (seg == 0) ? g_csr_fwd : (seg == 1) ? g_csr_rev : g_csr_rs;
    const float* feat = (seg == 2) ? g_hr : g_hs;

    float ax = 0.f, ay = 0.f, bx = 0.f, by = 0.f;
    int e = start;
    for (; e + 1 < end; e += 2) {
        int n0 = __ldg(&lst[e]);
        int n1 = __ldg(&lst[e + 1]);
        float2 v0 = *(const float2*)&feat[n0 * H + lane * 2];
        float2 v1 = *(const float2*)&feat[n1 * H + lane * 2];
        ax += v0.x; ay += v0.y;
        bx += v1.x; by += v1.y;
    }
    if (e < end) {
        int n0 = __ldg(&lst[e]);
        float2 v0 = *(const float2*)&feat[n0 * H + lane * 2];
        ax += v0.x; ay += v0.y;
    }
    ax += bx; ay += by;
    float inv = (end > start) ? __fdividef(1.f, (float)(end - start)) : 0.f;
    float* out = (seg == 0) ? g_afwd : (seg == 1) ? g_arev : g_ars;
    *(float2*)&out[node * H + lane * 2] = make_float2(ax * inv, ay * inv);
}

// ---------------- mma.sync LSTM: ldmatrix A-loads + LDS.128 B-frags ----------------
#define LS_M 80
#define LS_THREADS 256
#define LS_BLOCKS_S (NSTORE / LS_M)   // 250
#define LS_BLOCKS_R (NREG / LS_M)     // 25

#define OFF_WFRAG 0                   // 16384 u32 = 64 KB
#define OFF_HHI   65536               // 80 x 72 bf16 = 11520 B
#define OFF_HLO   (OFF_HHI + 11520)
#define OFF_XT    (OFF_HLO + 11520)   // 24 x 80 f32
#define OFF_WIN   (OFF_XT + 7680)
#define OFF_BG    (OFF_WIN + 1024)
#define LS_SMEM   (OFF_BG + 1024)     // 98304 B

__global__ __launch_bounds__(LS_THREADS, 2)
void lstm_mma_kernel(const float* __restrict__ x_s, const float* __restrict__ x_r,
                     const float* __restrict__ Wih_s, const float* __restrict__ Whh_s,
                     const float* __restrict__ bih_s, const float* __restrict__ bhh_s,
                     const float* __restrict__ Wih_r, const float* __restrict__ Whh_r,
                     const float* __restrict__ bih_r, const float* __restrict__ bhh_r)
{
    extern __shared__ char smem[];
    uint32_t* Wfrag = (uint32_t*)(smem + OFF_WFRAG);
    __nv_bfloat16* hHi = (__nv_bfloat16*)(smem + OFF_HHI);
    __nv_bfloat16* hLo = (__nv_bfloat16*)(smem + OFF_HLO);
    float* xT   = (float*)(smem + OFF_XT);
    float* winG = (float*)(smem + OFF_WIN);
    float* bG   = (float*)(smem + OFF_BG);

    const int tid = threadIdx.x;
    const bool is_store = (blockIdx.x < LS_BLOCKS_S);
    const int lb = is_store ? blockIdx.x : (blockIdx.x - LS_BLOCKS_S);
    const float* x   = is_store ? x_s   : x_r;
    const float* Wih = is_store ? Wih_s : Wih_r;
    const float* Whh = is_store ? Whh_s : Whh_r;
    const float* bih = is_store ? bih_s : bih_r;
    const float* bhh = is_store ? bhh_s : bhh_r;
    float* hout = is_store ? g_hs : g_hr;
    const int s0 = lb * LS_M;

    // ---- build W fragments: [half][ks][nt][lane][q] with q = (hi0,hi1,lo0,lo1) ----
    for (int idx = tid; idx < 16384; idx += LS_THREADS) {
        int q    = idx & 3;
        int ln   = (idx >> 2) & 31;
        int nt   = (idx >> 7) & 15;
        int ks   = (idx >> 11) & 3;
        int half = (idx >> 13) & 1;
        int hl = q >> 1, reg = q & 1;
        int tgi = ln & 3, gidi = ln >> 2;
        int gate = (nt & 1) * 2 + (gidi & 1);
        int unit = half * 32 + (nt >> 1) * 4 + (gidi >> 1);
        int row = gate * 64 + unit;
        int k = ks * 16 + tgi * 2 + reg * 8;
        float w0 = Whh[row * 64 + k];
        float w1 = Whh[row * 64 + k + 1];
        __nv_bfloat16 h0 = __float2bfloat16(w0);
        __nv_bfloat16 h1 = __float2bfloat16(w1);
        uint32_t val;
        if (hl == 0) {
            val = (uint32_t)__bfloat16_as_ushort(h0)
                | ((uint32_t)__bfloat16_as_ushort(h1) << 16);
        } else {
            __nv_bfloat16 l0 = __float2bfloat16(w0 - __bfloat162float(h0));
            __nv_bfloat16 l1 = __float2bfloat16(w1 - __bfloat162float(h1));
            val = (uint32_t)__bfloat16_as_ushort(l0)
                | ((uint32_t)__bfloat16_as_ushort(l1) << 16);
        }
        Wfrag[idx] = val;
    }
    if (tid < 256) {
        int half = tid >> 7, rr = tid & 127;
        int nt = (rr >> 3) & 15, g8 = rr & 7;
        int gate = (nt & 1) * 2 + (g8 & 1);
        int unit = half * 32 + (nt >> 1) * 4 + (g8 >> 1);
        winG[tid] = Wih[gate * 64 + unit];
        bG[tid]   = bih[gate * 64 + unit] + bhh[gate * 64 + unit];
    }
    for (int i = tid; i < 23040 / 4; i += LS_THREADS)
        ((uint32_t*)(smem + OFF_HHI))[i] = 0;
    for (int i = tid; i < LS_M * TS; i += LS_THREADS) {
        int s = i / TS, t = i % TS;
        xT[t * LS_M + s] = x[(s0 + s) * TS + t];
    }
    __syncthreads();

    const int warp = tid >> 5, lane = tid & 31;
    const int tg = lane & 3, gid = lane >> 2;

    // ldmatrix per-lane base (proven R12 mapping)
    const int mat = lane >> 3, r8 = lane & 7;
    const uint32_t sbase32 = (uint32_t)__cvta_generic_to_shared(smem);
    const uint32_t aoff = (uint32_t)(((mat & 1) * 8 + r8) * 144 + (mat >> 1) * 16);
    const uint32_t aHiB = sbase32 + OFF_HHI + aoff;
    const uint32_t aLoB = sbase32 + OFF_HLO + aoff;

    float cst[2][10];
#pragma unroll
    for (int i = 0; i < 10; i++) { cst[0][i] = 0.f; cst[1][i] = 0.f; }

    for (int t = 0; t < TS; t++) {
        float hn[2][10];
#pragma unroll
        for (int half = 0; half < 2; half++) {
            float acc[5][2][4];
#pragma unroll
            for (int t01 = 0; t01 < 2; t01++) {
                int r0 = half * 128 + (2 * warp + t01) * 8 + 2 * tg;
                float w0 = winG[r0], w1 = winG[r0 + 1];
                float bb0 = bG[r0], bb1 = bG[r0 + 1];
#pragma unroll
                for (int mt = 0; mt < 5; mt++) {
                    float xa = xT[t * LS_M + mt * 16 + gid];
                    float xb = xT[t * LS_M + mt * 16 + gid + 8];
                    acc[mt][t01][0] = fmaf(xa, w0, bb0);
                    acc[mt][t01][1] = fmaf(xa, w1, bb1);
                    acc[mt][t01][2] = fmaf(xb, w0, bb0);
                    acc[mt][t01][3] = fmaf(xb, w1, bb1);
                }
            }
#pragma unroll
            for (int ks = 0; ks < 4; ks++) {
                uint32_t a[5][4];
#pragma unroll
                for (int mt = 0; mt < 5; mt++)
                    ldsm_x4(a[mt], aHiB + mt * 2304 + ks * 32);
                uint32_t bhi[2][2], blo[2][2];
#pragma unroll
                for (int t01 = 0; t01 < 2; t01++) {
                    int nt = 2 * warp + t01;
                    uint4 w4 = *(const uint4*)&Wfrag[((((half * 4 + ks) * 16 + nt) * 32) + lane) * 4];
                    bhi[t01][0] = w4.x; bhi[t01][1] = w4.y;
                    blo[t01][0] = w4.z; blo[t01][1] = w4.w;
                }
#pragma unroll
                for (int mt = 0; mt < 5; mt++) {
                    MMA_BF16(acc[mt][0], a[mt], bhi[0]);
                    MMA_BF16(acc[mt][1], a[mt], bhi[1]);
                    MMA_BF16(acc[mt][0], a[mt], blo[0]);
                    MMA_BF16(acc[mt][1], a[mt], blo[1]);
                }
#pragma unroll
                for (int mt = 0; mt < 5; mt++)
                    ldsm_x4(a[mt], aLoB + mt * 2304 + ks * 32);
#pragma unroll
                for (int mt = 0; mt < 5; mt++) {
                    MMA_BF16(acc[mt][0], a[mt], bhi[0]);
                    MMA_BF16(acc[mt][1], a[mt], bhi[1]);
                }
            }
#pragma unroll
            for (int mt = 0; mt < 5; mt++) {
#pragma unroll
                for (int sb = 0; sb < 2; sb++) {
                    float gi = acc[mt][0][sb * 2 + 0];
                    float gf = acc[mt][0][sb * 2 + 1];
                    float gg = acc[mt][1][sb * 2 + 0];
                    float go = acc[mt][1][sb * 2 + 1];
                    float cc = cst[half][mt * 2 + sb];
                    cc = sigf(gf) * cc + sigf(gi) * tanh_fast(gg);
                    cst[half][mt * 2 + sb] = cc;
                    hn[half][mt * 2 + sb] = sigf(go) * tanh_fast(cc);
                }
            }
        }
        __syncthreads();
#pragma unroll
        for (int half = 0; half < 2; half++) {
            int u = half * 32 + warp * 4 + tg;
#pragma unroll
            for (int mt = 0; mt < 5; mt++) {
#pragma unroll
                for (int sb = 0; sb < 2; sb++) {
                    int s = mt * 16 + gid + sb * 8;
                    float h = hn[half][mt * 2 + sb];
                    __nv_bfloat16 hh = __float2bfloat16(h);
                    __nv_bfloat16 hl = __float2bfloat16(h - __bfloat162float(hh));
                    hHi[s * 72 + u] = hh;
                    hLo[s * 72 + u] = hl;
                    if (t == TS - 1) hout[(s0 + s) * H + u] = h;
                }
            }
        }
        __syncthreads();
    }
}

// ---------------- fused finalize ----------------
#define FIN_NODES 16
#define FIN_THREADS 1024
#define FIN_WS 65
#define FIN_SMEM_FLOATS (5 * H * FIN_WS + FIN_NODES * 4 * H + FIN_NODES * H + 2 * H)

__global__ __launch_bounds__(FIN_THREADS, 1)
void finalize_kernel(const float* __restrict__ W_s2d, const float* __restrict__ b_s2d,
                     const float* __restrict__ W_d2s, const float* __restrict__ b_d2s,
                     const float* __restrict__ W_self, const float* __restrict__ b_self,
                     const float* __restrict__ Wl_rs, const float* __restrict__ bl_rs,
                     const float* __restrict__ Wr_rs,
                     const float* __restrict__ Wf, const float* __restrict__ bf,
                     float* __restrict__ out)
{
    extern __shared__ float smemf[];
    float* Wsum = smemf;
    float* Wa   = Wsum + H * FIN_WS;
    float* Wb   = Wa + H * FIN_WS;
    float* Wc   = Wb + H * FIN_WS;
    float* Wfo  = Wc + H * FIN_WS;
    float* vec  = Wfo + H * FIN_WS;
    float* shm  = vec + FIN_NODES * 4 * H;
    float* btot = shm + FIN_NODES * H;
    float* bfv  = btot + H;

    const int tid = threadIdx.x;
    const int n0 = blockIdx.x * FIN_NODES;

    for (int i = tid; i < H * H; i += FIN_THREADS) {
        int r = i >> 6, cix = i & 63;
        Wsum[r * FIN_WS + cix] = W_self[i] + Wr_rs[i];
        Wa[r * FIN_WS + cix]   = W_s2d[i];
        Wb[r * FIN_WS + cix]   = W_d2s[i];
        Wc[r * FIN_WS + cix]   = Wl_rs[i];
        Wfo[r * FIN_WS + cix]  = Wf[i];
    }
    if (tid < H) {
        btot[tid] = b_self[tid] + bl_rs[tid]
                  + (1.f - ALPHA) * b_s2d[tid] + ALPHA * b_d2s[tid];
        bfv[tid] = bf[tid];
    }
    for (int i = tid; i < FIN_NODES * 4 * H; i += FIN_THREADS) {
        int n = i >> 8, v = (i >> 6) & 3, k = i & 63;
        int node = n0 + n;
        float val = 0.f;
        if (node < NSTORE) {
            if (v == 0)      val = g_hs[node * H + k];
            else if (v == 1) val = (1.f - ALPHA) * g_afwd[node * H + k];
            else if (v == 2) val = ALPHA * g_arev[node * H + k];
            else             val = g_ars[node * H + k];
        }
        vec[i] = val;
    }
    __syncthreads();

    const int n = tid >> 6, u = tid & 63;
    const float* v0 = &vec[(n * 4 + 0) * H];
    const float* v1 = &vec[(n * 4 + 1) * H];
    const float* v2 = &vec[(n * 4 + 2) * H];
    const float* v3 = &vec[(n * 4 + 3) * H];

    float acc = btot[u];
#pragma unroll 8
    for (int k = 0; k < H; k++) {
        acc = fmaf(v0[k], Wsum[u * FIN_WS + k], acc);
        acc = fmaf(v1[k], Wa[u * FIN_WS + k], acc);
        acc = fmaf(v2[k], Wb[u * FIN_WS + k], acc);
        acc = fmaf(v3[k], Wc[u * FIN_WS + k], acc);
    }
    float sh = fmaxf(0.f, v0[u] + 0.5f * acc);
    shm[n * H + u] = sh;
    __syncthreads();

    float acc2 = bfv[u];
#pragma unroll 8
    for (int k = 0; k < H; k++)
        acc2 = fmaf(Wfo[u * FIN_WS + k], shm[n * H + k], acc2);

    int node = n0 + n;
    if (node < NSTORE) out[node * H + u] = acc2;
}

// ---------------- launch ----------------
extern "C" void kernel_launch(void* const* d_in, const int* in_sizes, int n_in,
                              void* d_out, int out_size)
{
    const float* x_store  = (const float*)d_in[0];
    const float* x_region = (const float*)d_in[1];
    const int* ess    = (const int*)d_in[2];
    const int* rs_src = (const int*)d_in[3];
    const int* rs_dst = (const int*)d_in[4];
    const float* Wih_s = (const float*)d_in[7];
    const float* Whh_s = (const float*)d_in[8];
    const float* bih_s = (const float*)d_in[9];
    const float* bhh_s = (const float*)d_in[10];
    const float* Wih_r = (const float*)d_in[11];
    const float* Whh_r = (const float*)d_in[12];
    const float* bih_r = (const float*)d_in[13];
    const float* bhh_r = (const float*)d_in[14];
    const float* W_s2d = (const float*)d_in[15];
    const float* b_s2d = (const float*)d_in[16];
    const float* W_d2s = (const float*)d_in[17];
    const float* b_d2s = (const float*)d_in[18];
    const float* W_self = (const float*)d_in[19];
    const float* b_self = (const float*)d_in[20];
    const float* Wl_rs = (const float*)d_in[21];
    const float* bl_rs = (const float*)d_in[22];
    const float* Wr_rs = (const float*)d_in[23];
    const float* Wf = (const float*)d_in[27];
    const float* bf = (const float*)d_in[28];

    static cudaStream_t s_side = nullptr;
    static cudaEvent_t ev_fork = nullptr, ev_join = nullptr;
    if (!s_side) {
        cudaStreamCreateWithFlags(&s_side, cudaStreamNonBlocking);
        cudaEventCreateWithFlags(&ev_fork, cudaEventDisableTiming);
        cudaEventCreateWithFlags(&ev_join, cudaEventDisableTiming);
    }

    const size_t fin_smem = FIN_SMEM_FLOATS * sizeof(float);
    cudaFuncSetAttribute(lstm_mma_kernel, cudaFuncAttributeMaxDynamicSharedMemorySize, LS_SMEM);
    cudaFuncSetAttribute(finalize_kernel, cudaFuncAttributeMaxDynamicSharedMemorySize, (int)fin_smem);

    // Fork first (topology), but enqueue the LSTM BEFORE the CSR chain so the
    // graph executor dispatches the LSTM's blocks first; CSR fills spare slots.
    cudaEventRecord(ev_fork, 0);
    cudaStreamWaitEvent(s_side, ev_fork, 0);

    lstm_mma_kernel<<<LS_BLOCKS_S + LS_BLOCKS_R, LS_THREADS, LS_SMEM>>>(
        x_store, x_region,
        Wih_s, Whh_s, bih_s, bhh_s,
        Wih_r, Whh_r, bih_r, bhh_r);

    zero_cnt_kernel<<<(3 * NSTORE + 255) / 256, 256, 0, s_side>>>();
    count_kernel<<<(E_SS + 255) / 256, 256, 0, s_side>>>(ess, ess + E_SS, rs_dst);
    scan_kernel<<<3, 1024, 0, s_side>>>();
    scatter_kernel<<<(E_SS + 255) / 256, 256, 0, s_side>>>(ess, ess + E_SS, rs_src, rs_dst);

    cudaEventRecord(ev_join, s_side);
    cudaStreamWaitEvent(0, ev_join, 0);

    gather_kernel<<<(3 * NSTORE + GATHER_WARPS - 1) / GATHER_WARPS, 256>>>();

    finalize_kernel<<<(NSTORE + FIN_NODES - 1) / FIN_NODES, FIN_THREADS, fin_smem>>>(
        W_s2d, b_s2d, W_d2s, b_d2s, W_self, b_self,
        Wl_rs, bl_rs, Wr_rs, Wf, bf, (float*)d_out);
}